// round 15
// baseline (speedup 1.0000x reference)
#include <cuda_runtime.h>
#include <cuda_bf16.h>
#include <cuda_fp16.h>
#include <math.h>

// Problem constants
#define B_DIM 4096
#define T_DIM 2048
#define N_ELEM (B_DIM * T_DIM)        // 8,388,608
#define GRID   888                     // 148 SMs x 6 CTAs; <=152x6 wave cap
#define FULL_ROWS_CTAS 544             // 544*5 + 344*4 = 4096
#define MAX_ROWS 5
static __device__ __constant__ const float kGamma = 0.99f;
static __device__ __constant__ const float kGL    = (float)(0.99 * 0.95);  // gamma*lam
static __device__ __constant__ const float kEps   = 1e-9f;

// Global state (no allocations allowed -> __device__ globals).
// Invariant: everything is ZERO on entry to each launch; the last CTA to
// finish phase B resets all of it after writing the output.
__device__ double            g_S1  = 0.0;   // sum(adv_raw)
__device__ double            g_S2  = 0.0;   // sum(adv_raw^2) == N * value_loss
__device__ double            g_MIN = 0.0;   // sum(min(surr1, surr2))
__device__ double            g_ENT = 0.0;   // sum(curr * log(curr + eps))
__device__ unsigned          g_arrive1 = 0u;  // phase-A barrier arrivals
__device__ unsigned          g_arrive2 = 0u;  // phase-B completion arrivals
__device__ volatile unsigned g_release = 0u;  // phase-A barrier release flag
__device__ volatile float    g_mean_f  = 0.f;
__device__ volatile float    g_scale_f = 0.f;

// ---------------------------------------------------------------------------
// ONE persistent kernel, 6 CTAs/SM for load parallelism. Phase A: GAE reverse
// scan per owned row, advantages stashed in SHARED memory (fp16). Grid
// barrier computes mean/std. Phase B: clipped surrogate + entropy.
// ---------------------------------------------------------------------------
__global__ __launch_bounds__(256, 6)
void ppo_fused_kernel(const float* __restrict__ rewards,
                      const float* __restrict__ values,
                      const float* __restrict__ masks,
                      const float* __restrict__ oldp,
                      const float* __restrict__ currp,
                      float* __restrict__ out)
{
    __shared__ __align__(16) __half s_adv[MAX_ROWS * T_DIM];  // 20 KB
    __shared__ float  wA[2][8], wP[2][8];    // double-buffered warp summaries
    __shared__ double sA[8], sB[8];
    __shared__ float  s_mean, s_scale;

    const int bid  = blockIdx.x;
    const int tid  = threadIdx.x;
    const int lane = tid & 31;
    const int warp = tid >> 5;
    const int t0   = tid << 3;                    // 8 elements per thread
    const unsigned full = 0xffffffffu;

    const int nrows = (bid < FULL_ROWS_CTAS) ? MAX_ROWS : (MAX_ROWS - 1);

    // ===================== Phase A: GAE scan per row =====================
    double dS1 = 0.0, dS2 = 0.0;                  // per-thread across rows

    for (int i = 0; i < nrows; ++i) {
        const int b = bid + i * GRID;
        const int buf = i & 1;

        const float* rr = rewards + (size_t)b * T_DIM + t0;
        const float* mm = masks   + (size_t)b * T_DIM + t0;
        const float* vv = values  + (size_t)b * (T_DIM + 1) + t0;

        float4 rA = __ldcs((const float4*)(rr));
        float4 rB = __ldcs((const float4*)(rr + 4));
        float4 mA = __ldcs((const float4*)(mm));
        float4 mB = __ldcs((const float4*)(mm + 4));

        float v[9];
        #pragma unroll
        for (int j = 0; j < 9; ++j) v[j] = __ldcs(vv + j);   // row stride 2049

        float r[8] = {rA.x, rA.y, rA.z, rA.w, rB.x, rB.y, rB.z, rB.w};
        float m[8] = {mA.x, mA.y, mA.z, mA.w, mB.x, mB.y, mB.z, mB.w};

        // delta reused in-place as av later; c = gamma*lam*mask
        float delta[8], c[8];
        #pragma unroll
        for (int j = 0; j < 8; ++j) {
            delta[j] = r[j] + kGamma * v[j + 1] * m[j] - v[j];
            c[j]     = kGL * m[j];
        }

        // Thread-local reverse scan summary (A, P): x -> A + P*x
        float A = 0.f, P = 1.f;
        #pragma unroll
        for (int j = 7; j >= 0; --j) { A = delta[j] + c[j] * A; P *= c[j]; }

        // Warp inclusive SUFFIX scan (higher lanes = higher t, applied first)
        float Ai = A, Pi = P;
        #pragma unroll
        for (int d = 1; d < 32; d <<= 1) {
            float Ah = __shfl_down_sync(full, Ai, d);
            float Ph = __shfl_down_sync(full, Pi, d);
            if (lane + d < 32) { Ai = Ai + Pi * Ah; Pi = Pi * Ph; }
        }

        if (lane == 0) { wA[buf][warp] = Ai; wP[buf][warp] = Pi; }
        __syncthreads();   // one barrier per row (alternating buffers)

        // Carry entering this warp: compose warps 7..warp+1 applied to 0
        float warpCarry = 0.f;
        #pragma unroll
        for (int w = 7; w >= 0; --w)
            if (w > warp) warpCarry = wA[buf][w] + wP[buf][w] * warpCarry;

        // Exclusive-within-warp transform = inclusive suffix of lane+1
        float Ae = __shfl_down_sync(full, Ai, 1);
        float Pe = __shfl_down_sync(full, Pi, 1);
        if (lane == 31) { Ae = 0.f; Pe = 1.f; }
        float carry = Ae + Pe * warpCarry;

        // Final local values with real carry (in place into delta[])
        {
            float a = carry;
            #pragma unroll
            for (int j = 7; j >= 0; --j) { a = delta[j] + c[j] * a; delta[j] = a; }
        }

        // Stash advantages in shared memory as fp16 (one 16B STS)
        {
            __half2 h01 = __floats2half2_rn(delta[0], delta[1]);
            __half2 h23 = __floats2half2_rn(delta[2], delta[3]);
            __half2 h45 = __floats2half2_rn(delta[4], delta[5]);
            __half2 h67 = __floats2half2_rn(delta[6], delta[7]);
            uint4 pk;
            pk.x = *reinterpret_cast<unsigned*>(&h01);
            pk.y = *reinterpret_cast<unsigned*>(&h23);
            pk.z = *reinterpret_cast<unsigned*>(&h45);
            pk.w = *reinterpret_cast<unsigned*>(&h67);
            ((uint4*)s_adv)[(i * T_DIM + t0) >> 3] = pk;
        }

        // Accumulate sum/sumsq from full-precision adv (exact value_loss)
        float fs = 0.f, fq = 0.f;
        #pragma unroll
        for (int j = 0; j < 8; ++j) { fs += delta[j]; fq += delta[j] * delta[j]; }
        dS1 += (double)fs;
        dS2 += (double)fq;
    }

    // Block-reduce S1/S2 (double), one atomic pair per CTA
    #pragma unroll
    for (int d = 16; d > 0; d >>= 1) {
        dS1 += __shfl_down_sync(full, dS1, d);
        dS2 += __shfl_down_sync(full, dS2, d);
    }
    if (lane == 0) { sA[warp] = dS1; sB[warp] = dS2; }
    __syncthreads();
    if (tid == 0) {
        double ts = 0.0, tq = 0.0;
        #pragma unroll
        for (int w = 0; w < 8; ++w) { ts += sA[w]; tq += sB[w]; }
        atomicAdd(&g_S1, ts);
        atomicAdd(&g_S2, tq);
    }

    // ===================== Grid-wide barrier + mean/std ==================
    if (tid == 0) {
        __threadfence();                          // order S1/S2 before arrival
        unsigned ticket = atomicAdd(&g_arrive1, 1u);
        if (ticket == (unsigned)(GRID - 1)) {
            double ts1 = atomicAdd(&g_S1, 0.0);   // coherent reads
            double ts2 = atomicAdd(&g_S2, 0.0);
            const double N = (double)N_ELEM;
            double mean = ts1 / N;
            double var  = (ts2 - N * mean * mean) / (N - 1.0);  // ddof=1
            g_mean_f  = (float)mean;
            g_scale_f = (float)(1.0 / (sqrt(var) + 1e-9));
            __threadfence();
            g_release = 1u;
        } else {
            while (g_release == 0u) __nanosleep(64);
            __threadfence();
        }
        s_mean  = g_mean_f;
        s_scale = g_scale_f;
    }
    __syncthreads();
    const float mean  = s_mean;
    const float scale = s_scale;

    // ===================== Phase B: surrogate + entropy ==================
    // min(surr1,surr2) = a>=0 ? min(ratio,1.2)*a : max(ratio,0.8)*a
    float fmin_acc = 0.f, fent_acc = 0.f;

    for (int i = 0; i < nrows; ++i) {
        const int b = bid + i * GRID;
        const float4* op = (const float4*)(oldp  + (size_t)b * T_DIM + t0);
        const float4* cp = (const float4*)(currp + (size_t)b * T_DIM + t0);

        uint4  u  = ((const uint4*)s_adv)[(i * T_DIM + t0) >> 3];
        float4 o0 = __ldcs(op);
        float4 o1 = __ldcs(op + 1);
        float4 c0 = __ldcs(cp);
        float4 c1 = __ldcs(cp + 1);

        float2 a01 = __half22float2(*reinterpret_cast<__half2*>(&u.x));
        float2 a23 = __half22float2(*reinterpret_cast<__half2*>(&u.y));
        float2 a45 = __half22float2(*reinterpret_cast<__half2*>(&u.z));
        float2 a67 = __half22float2(*reinterpret_cast<__half2*>(&u.w));

        float av[8] = {a01.x, a01.y, a23.x, a23.y, a45.x, a45.y, a67.x, a67.y};
        float ov[8] = {o0.x, o0.y, o0.z, o0.w, o1.x, o1.y, o1.z, o1.w};
        float cv[8] = {c0.x, c0.y, c0.z, c0.w, c1.x, c1.y, c1.z, c1.w};

        #pragma unroll
        for (int k = 0; k < 8; ++k) {
            float an    = (av[k] - mean) * scale;
            float ratio = __fdividef(cv[k], ov[k] + kEps);
            float t = (an >= 0.f) ? fminf(ratio, 1.2f) * an
                                  : fmaxf(ratio, 0.8f) * an;
            fmin_acc += t;
            fent_acc += cv[k] * __logf(cv[k] + kEps);
        }
    }

    double lmin = (double)fmin_acc, lent = (double)fent_acc;
    #pragma unroll
    for (int d = 16; d > 0; d >>= 1) {
        lmin += __shfl_down_sync(full, lmin, d);
        lent += __shfl_down_sync(full, lent, d);
    }
    if (lane == 0) { sA[warp] = lmin; sB[warp] = lent; }
    __syncthreads();

    if (tid == 0) {
        double tm = 0.0, te = 0.0;
        #pragma unroll
        for (int w = 0; w < 8; ++w) { tm += sA[w]; te += sB[w]; }
        atomicAdd(&g_MIN, tm);
        atomicAdd(&g_ENT, te);
        __threadfence();                  // order loss atomics before arrival
        unsigned done = atomicAdd(&g_arrive2, 1u);
        if (done == (unsigned)(GRID - 1)) {
            // Last CTA: finalize output, reset ALL state for the next launch.
            double tmin = atomicAdd(&g_MIN, 0.0);
            double tent = atomicAdd(&g_ENT, 0.0);
            double ts2  = atomicAdd(&g_S2,  0.0);
            const double N = (double)N_ELEM;
            double ppo = -(tmin / N);
            double vl  = 0.5   * (ts2  / N);  // VALUE_LOSS_COEF * mean(adv^2)
            double ent = -0.01 * (tent / N);  // ENTROPY_COEF * entropy_loss
            out[0] = (float)(ppo + vl + ent);
            out[1] = (float)ppo;
            out[2] = (float)vl;
            out[3] = (float)ent;
            g_S1 = 0.0; g_S2 = 0.0; g_MIN = 0.0; g_ENT = 0.0;
            g_arrive1 = 0u; g_arrive2 = 0u;
            g_mean_f = 0.f; g_scale_f = 0.f;
            __threadfence();
            g_release = 0u;               // safe: every CTA is past barrier 1
        }
    }
}

extern "C" void kernel_launch(void* const* d_in, const int* in_sizes, int n_in,
                              void* d_out, int out_size)
{
    const float* rewards = (const float*)d_in[0];
    const float* values  = (const float*)d_in[1];
    // d_in[2] = ref_probs (unused by reference)
    const float* oldp    = (const float*)d_in[3];
    const float* currp   = (const float*)d_in[4];
    const float* masks   = (const float*)d_in[5];

    ppo_fused_kernel<<<GRID, 256>>>(rewards, values, masks, oldp, currp,
                                    (float*)d_out);
}

// round 16
// speedup vs baseline: 1.1881x; 1.1881x over previous
#include <cuda_runtime.h>
#include <cuda_bf16.h>
#include <cuda_fp16.h>
#include <math.h>

// Problem constants
#define B_DIM 4096
#define T_DIM 2048
#define N_ELEM (B_DIM * T_DIM)        // 8,388,608
#define GRID   592                     // 148 SMs x 4 CTAs -> single wave
#define FULL_ROWS_CTAS 544             // 544*7 + 48*6 = 4096
#define MAX_ROWS 7
#define VPAD 2305                      // 2049 values + idx/8 padding
static __device__ __constant__ const float kGamma = 0.99f;
static __device__ __constant__ const float kGL    = (float)(0.99 * 0.95);  // gamma*lam
static __device__ __constant__ const float kEps   = 1e-9f;

// Global state (no allocations allowed -> __device__ globals).
// Invariant: everything is ZERO on entry to each launch; the last CTA to
// finish phase B resets all of it after writing the output.
__device__ double            g_S1  = 0.0;   // sum(adv_raw)
__device__ double            g_S2  = 0.0;   // sum(adv_raw^2) == N * value_loss
__device__ double            g_MIN = 0.0;   // sum(min(surr1, surr2))
__device__ double            g_ENT = 0.0;   // sum(curr * log(curr + eps))
__device__ unsigned          g_arrive1 = 0u;  // phase-A barrier arrivals
__device__ unsigned          g_arrive2 = 0u;  // phase-B completion arrivals
__device__ volatile unsigned g_release = 0u;  // phase-A barrier release flag
__device__ volatile float    g_mean_f  = 0.f;
__device__ volatile float    g_scale_f = 0.f;

// Padded smem index for a values row: read stride becomes 9 floats
// (9 coprime to 32 -> conflict-free LDS across lanes).
__device__ __forceinline__ int vp(int idx) { return idx + (idx >> 3); }

#define CP_ASYNC_F32(saddr, gptr) \
    asm volatile("cp.async.ca.shared.global [%0], [%1], 4;" \
                 :: "r"(saddr), "l"(gptr) : "memory")
#define CP_COMMIT() asm volatile("cp.async.commit_group;" ::: "memory")
#define CP_WAIT0()  asm volatile("cp.async.wait_group 0;" ::: "memory")

// ---------------------------------------------------------------------------
// ONE persistent kernel (R12 skeleton). Phase A: GAE reverse scan per owned
// row; values rows double-buffer-staged via cp.async (coalesced, overlapped,
// non-bar-blocking); advantages stashed in smem (fp16). Grid barrier computes
// mean/std. Phase B: pipelined clipped surrogate + entropy.
// ---------------------------------------------------------------------------
__global__ __launch_bounds__(256, 4)
void ppo_fused_kernel(const float* __restrict__ rewards,
                      const float* __restrict__ values,
                      const float* __restrict__ masks,
                      const float* __restrict__ oldp,
                      const float* __restrict__ currp,
                      float* __restrict__ out)
{
    __shared__ __align__(16) __half s_adv[MAX_ROWS * T_DIM];  // 28 KB
    __shared__ __align__(16) float  s_val[2][VPAD];           // 18.4 KB
    __shared__ float  wA[2][8], wP[2][8];
    __shared__ double sA[8], sB[8];
    __shared__ float  s_mean, s_scale;

    const int bid  = blockIdx.x;
    const int tid  = threadIdx.x;
    const int lane = tid & 31;
    const int warp = tid >> 5;
    const int t0   = tid << 3;                    // 8 elements per thread
    const unsigned full = 0xffffffffu;

    const int nrows = (bid < FULL_ROWS_CTAS) ? MAX_ROWS : (MAX_ROWS - 1);

    // ===================== Phase A: GAE scan per row =====================
    double dS1 = 0.0, dS2 = 0.0;

    // Prologue: stage row 0's values into buffer 0 via cp.async
    {
        const float* vrow = values + (size_t)bid * (T_DIM + 1);
        unsigned base = (unsigned)__cvta_generic_to_shared(&s_val[0][0]);
        #pragma unroll
        for (int j = 0; j < 8; ++j) {
            int st = tid + j * 256;
            CP_ASYNC_F32(base + (unsigned)vp(st) * 4u, vrow + st);
        }
        if (tid == 0) CP_ASYNC_F32(base + (unsigned)vp(2048) * 4u, vrow + 2048);
        CP_COMMIT();
    }

    for (int i = 0; i < nrows; ++i) {
        const int b   = bid + i * GRID;
        const int buf = i & 1;

        // Independent coalesced loads first (overlap with cp.async wait)
        const float* rr = rewards + (size_t)b * T_DIM + t0;
        const float* mm = masks   + (size_t)b * T_DIM + t0;
        float4 rA = __ldcs((const float4*)(rr));
        float4 rB = __ldcs((const float4*)(rr + 4));
        float4 mA = __ldcs((const float4*)(mm));
        float4 mB = __ldcs((const float4*)(mm + 4));

        CP_WAIT0();          // this row's values staged (this thread's view)
        __syncthreads();     // all threads' cp.async visible; prev row done

        // Read this row's values from padded smem (conflict-free, stride 9)
        float v[9];
        {
            const int vb = 9 * tid;
            #pragma unroll
            for (int j = 0; j < 8; ++j) v[j] = s_val[buf][vb + j];
            v[8] = s_val[buf][vb + 9];           // vp(t0+8) = 9*tid + 9
        }

        // Kick off NEXT row's values staging into the other buffer
        if (i + 1 < nrows) {
            const float* vrow2 = values + (size_t)(b + GRID) * (T_DIM + 1);
            unsigned base2 = (unsigned)__cvta_generic_to_shared(&s_val[buf ^ 1][0]);
            #pragma unroll
            for (int j = 0; j < 8; ++j) {
                int st = tid + j * 256;
                CP_ASYNC_F32(base2 + (unsigned)vp(st) * 4u, vrow2 + st);
            }
            if (tid == 0) CP_ASYNC_F32(base2 + (unsigned)vp(2048) * 4u, vrow2 + 2048);
            CP_COMMIT();
        }

        float r[8] = {rA.x, rA.y, rA.z, rA.w, rB.x, rB.y, rB.z, rB.w};
        float m[8] = {mA.x, mA.y, mA.z, mA.w, mB.x, mB.y, mB.z, mB.w};

        float delta[8], c[8];
        #pragma unroll
        for (int j = 0; j < 8; ++j) {
            delta[j] = r[j] + kGamma * v[j + 1] * m[j] - v[j];
            c[j]     = kGL * m[j];
        }

        // Thread-local reverse scan summary (A, P): x -> A + P*x
        float A = 0.f, P = 1.f;
        #pragma unroll
        for (int j = 7; j >= 0; --j) { A = delta[j] + c[j] * A; P *= c[j]; }

        // Warp inclusive SUFFIX scan (higher lanes = higher t, applied first)
        float Ai = A, Pi = P;
        #pragma unroll
        for (int d = 1; d < 32; d <<= 1) {
            float Ah = __shfl_down_sync(full, Ai, d);
            float Ph = __shfl_down_sync(full, Pi, d);
            if (lane + d < 32) { Ai = Ai + Pi * Ah; Pi = Pi * Ph; }
        }

        if (lane == 0) { wA[buf][warp] = Ai; wP[buf][warp] = Pi; }
        __syncthreads();     // wA/wP[buf] ready (double-buffered per parity)

        // Carry entering this warp: compose warps 7..warp+1 applied to 0
        float warpCarry = 0.f;
        #pragma unroll
        for (int w = 7; w >= 0; --w)
            if (w > warp) warpCarry = wA[buf][w] + wP[buf][w] * warpCarry;

        // Exclusive-within-warp transform = inclusive suffix of lane+1
        float Ae = __shfl_down_sync(full, Ai, 1);
        float Pe = __shfl_down_sync(full, Pi, 1);
        if (lane == 31) { Ae = 0.f; Pe = 1.f; }
        float carry = Ae + Pe * warpCarry;

        // Final local values with real carry (in place into delta[])
        {
            float a = carry;
            #pragma unroll
            for (int j = 7; j >= 0; --j) { a = delta[j] + c[j] * a; delta[j] = a; }
        }

        // Stash advantages in shared memory as fp16 (one 16B STS)
        {
            __half2 h01 = __floats2half2_rn(delta[0], delta[1]);
            __half2 h23 = __floats2half2_rn(delta[2], delta[3]);
            __half2 h45 = __floats2half2_rn(delta[4], delta[5]);
            __half2 h67 = __floats2half2_rn(delta[6], delta[7]);
            uint4 pk;
            pk.x = *reinterpret_cast<unsigned*>(&h01);
            pk.y = *reinterpret_cast<unsigned*>(&h23);
            pk.z = *reinterpret_cast<unsigned*>(&h45);
            pk.w = *reinterpret_cast<unsigned*>(&h67);
            ((uint4*)s_adv)[(i * T_DIM + t0) >> 3] = pk;
        }

        // Accumulate sum/sumsq from full-precision adv (exact value_loss)
        float fs = 0.f, fq = 0.f;
        #pragma unroll
        for (int j = 0; j < 8; ++j) { fs += delta[j]; fq += delta[j] * delta[j]; }
        dS1 += (double)fs;
        dS2 += (double)fq;
    }

    // Block-reduce S1/S2 (double), one atomic pair per CTA
    #pragma unroll
    for (int d = 16; d > 0; d >>= 1) {
        dS1 += __shfl_down_sync(full, dS1, d);
        dS2 += __shfl_down_sync(full, dS2, d);
    }
    if (lane == 0) { sA[warp] = dS1; sB[warp] = dS2; }
    __syncthreads();
    if (tid == 0) {
        double ts = 0.0, tq = 0.0;
        #pragma unroll
        for (int w = 0; w < 8; ++w) { ts += sA[w]; tq += sB[w]; }
        atomicAdd(&g_S1, ts);
        atomicAdd(&g_S2, tq);
    }

    // Prefetch phase B's first row while the grid barrier settles
    const float4* op_pf = (const float4*)(oldp  + (size_t)bid * T_DIM + t0);
    const float4* cp_pf = (const float4*)(currp + (size_t)bid * T_DIM + t0);
    float4 o0 = __ldcs(op_pf);
    float4 o1 = __ldcs(op_pf + 1);
    float4 c0 = __ldcs(cp_pf);
    float4 c1 = __ldcs(cp_pf + 1);

    // ===================== Grid-wide barrier + mean/std ==================
    if (tid == 0) {
        __threadfence();                          // order S1/S2 before arrival
        unsigned ticket = atomicAdd(&g_arrive1, 1u);
        if (ticket == (unsigned)(GRID - 1)) {
            double ts1 = atomicAdd(&g_S1, 0.0);   // coherent reads
            double ts2 = atomicAdd(&g_S2, 0.0);
            const double N = (double)N_ELEM;
            double mean = ts1 / N;
            double var  = (ts2 - N * mean * mean) / (N - 1.0);  // ddof=1
            g_mean_f  = (float)mean;
            g_scale_f = (float)(1.0 / (sqrt(var) + 1e-9));
            __threadfence();
            g_release = 1u;
        } else {
            while (g_release == 0u) __nanosleep(64);
            __threadfence();
        }
        s_mean  = g_mean_f;
        s_scale = g_scale_f;
    }
    __syncthreads();
    const float mean  = s_mean;
    const float scale = s_scale;

    // ===================== Phase B: surrogate + entropy ==================
    // min(surr1,surr2) = a>=0 ? min(ratio,1.2)*a : max(ratio,0.8)*a
    float fmin_acc = 0.f, fent_acc = 0.f;

    for (int i = 0; i < nrows; ++i) {
        // Kick off next row's loads before consuming this row
        float4 no0, no1, nc0, nc1;
        if (i + 1 < nrows) {
            const int bn = bid + (i + 1) * GRID;
            const float4* opn = (const float4*)(oldp  + (size_t)bn * T_DIM + t0);
            const float4* cpn = (const float4*)(currp + (size_t)bn * T_DIM + t0);
            no0 = __ldcs(opn);
            no1 = __ldcs(opn + 1);
            nc0 = __ldcs(cpn);
            nc1 = __ldcs(cpn + 1);
        }

        uint4 u = ((const uint4*)s_adv)[(i * T_DIM + t0) >> 3];
        float2 a01 = __half22float2(*reinterpret_cast<__half2*>(&u.x));
        float2 a23 = __half22float2(*reinterpret_cast<__half2*>(&u.y));
        float2 a45 = __half22float2(*reinterpret_cast<__half2*>(&u.z));
        float2 a67 = __half22float2(*reinterpret_cast<__half2*>(&u.w));

        float av[8] = {a01.x, a01.y, a23.x, a23.y, a45.x, a45.y, a67.x, a67.y};
        float ov[8] = {o0.x, o0.y, o0.z, o0.w, o1.x, o1.y, o1.z, o1.w};
        float cv[8] = {c0.x, c0.y, c0.z, c0.w, c1.x, c1.y, c1.z, c1.w};

        #pragma unroll
        for (int k = 0; k < 8; ++k) {
            float an    = (av[k] - mean) * scale;
            float ratio = __fdividef(cv[k], ov[k] + kEps);
            float t = (an >= 0.f) ? fminf(ratio, 1.2f) * an
                                  : fmaxf(ratio, 0.8f) * an;
            fmin_acc += t;
            fent_acc += cv[k] * __logf(cv[k] + kEps);
        }

        o0 = no0; o1 = no1; c0 = nc0; c1 = nc1;
    }

    double lmin = (double)fmin_acc, lent = (double)fent_acc;
    #pragma unroll
    for (int d = 16; d > 0; d >>= 1) {
        lmin += __shfl_down_sync(full, lmin, d);
        lent += __shfl_down_sync(full, lent, d);
    }
    if (lane == 0) { sA[warp] = lmin; sB[warp] = lent; }
    __syncthreads();

    if (tid == 0) {
        double tm = 0.0, te = 0.0;
        #pragma unroll
        for (int w = 0; w < 8; ++w) { tm += sA[w]; te += sB[w]; }
        atomicAdd(&g_MIN, tm);
        atomicAdd(&g_ENT, te);
        __threadfence();                  // order loss atomics before arrival
        unsigned done = atomicAdd(&g_arrive2, 1u);
        if (done == (unsigned)(GRID - 1)) {
            // Last CTA: finalize output, reset ALL state for the next launch.
            double tmin = atomicAdd(&g_MIN, 0.0);
            double tent = atomicAdd(&g_ENT, 0.0);
            double ts2  = atomicAdd(&g_S2,  0.0);
            const double N = (double)N_ELEM;
            double ppo = -(tmin / N);
            double vl  = 0.5   * (ts2  / N);  // VALUE_LOSS_COEF * mean(adv^2)
            double ent = -0.01 * (tent / N);  // ENTROPY_COEF * entropy_loss
            out[0] = (float)(ppo + vl + ent);
            out[1] = (float)ppo;
            out[2] = (float)vl;
            out[3] = (float)ent;
            g_S1 = 0.0; g_S2 = 0.0; g_MIN = 0.0; g_ENT = 0.0;
            g_arrive1 = 0u; g_arrive2 = 0u;
            g_mean_f = 0.f; g_scale_f = 0.f;
            __threadfence();
            g_release = 0u;               // safe: every CTA is past barrier 1
        }
    }
}

extern "C" void kernel_launch(void* const* d_in, const int* in_sizes, int n_in,
                              void* d_out, int out_size)
{
    const float* rewards = (const float*)d_in[0];
    const float* values  = (const float*)d_in[1];
    // d_in[2] = ref_probs (unused by reference)
    const float* oldp    = (const float*)d_in[3];
    const float* currp   = (const float*)d_in[4];
    const float* masks   = (const float*)d_in[5];

    ppo_fused_kernel<<<GRID, 256>>>(rewards, values, masks, oldp, currp,
                                    (float*)d_out);
}

// round 17
// speedup vs baseline: 1.2840x; 1.0807x over previous
#include <cuda_runtime.h>
#include <cuda_bf16.h>
#include <cuda_fp16.h>
#include <math.h>

// Problem constants
#define B_DIM 4096
#define T_DIM 2048
#define N_ELEM (B_DIM * T_DIM)        // 8,388,608
#define GRID   592                     // 148 SMs x 4 CTAs -> single wave
#define FULL_ROWS_CTAS 544             // 544*7 + 48*6 = 4096
#define MAX_ROWS 7
#define VPAD 2305                      // 2049 values + idx/8 padding
static __device__ __constant__ const float kGamma = 0.99f;
static __device__ __constant__ const float kGL    = (float)(0.99 * 0.95);  // gamma*lam
static __device__ __constant__ const float kEps   = 1e-9f;

// Global state (no allocations allowed -> __device__ globals).
// Invariant: everything is ZERO on entry to each launch; the last CTA to
// finish phase B resets all of it after writing the output.
__device__ double            g_S1  = 0.0;   // sum(adv_raw)
__device__ double            g_S2  = 0.0;   // sum(adv_raw^2) == N * value_loss
__device__ double            g_MIN = 0.0;   // sum(min(surr1, surr2))
__device__ double            g_ENT = 0.0;   // sum(curr * log(curr + eps))
__device__ unsigned          g_arrive1 = 0u;  // phase-A barrier arrivals
__device__ unsigned          g_arrive2 = 0u;  // phase-B completion arrivals
__device__ volatile unsigned g_release = 0u;  // phase-A barrier release flag
__device__ volatile float    g_mean_f  = 0.f;
__device__ volatile float    g_scale_f = 0.f;

// Padded smem index for a values row: read stride becomes 9 floats
// (9 coprime to 32 -> conflict-free LDS across lanes).
__device__ __forceinline__ int vp(int idx) { return idx + (idx >> 3); }

#define CP_ASYNC_F32(saddr, gptr) \
    asm volatile("cp.async.ca.shared.global [%0], [%1], 4;" \
                 :: "r"(saddr), "l"(gptr) : "memory")
#define CP_COMMIT() asm volatile("cp.async.commit_group;" ::: "memory")
#define CP_WAIT0()  asm volatile("cp.async.wait_group 0;" ::: "memory")
#define L2_PREFETCH(p) \
    asm volatile("prefetch.global.L2 [%0];" :: "l"(p))

// ---------------------------------------------------------------------------
// ONE persistent kernel. Phase A: GAE reverse scan per owned row (values via
// cp.async double-buffer staging); WHILE scanning, prefetch this CTA's
// phase-B prob rows into L2 (67 MB total fits the 126 MB L2; phase-A streams
// are __ldcs evict-first and won't displace them). Grid barrier computes
// mean/std. Phase B: pipelined clipped surrogate + entropy, served from L2.
// ---------------------------------------------------------------------------
__global__ __launch_bounds__(256, 4)
void ppo_fused_kernel(const float* __restrict__ rewards,
                      const float* __restrict__ values,
                      const float* __restrict__ masks,
                      const float* __restrict__ oldp,
                      const float* __restrict__ currp,
                      float* __restrict__ out)
{
    __shared__ __align__(16) __half s_adv[MAX_ROWS * T_DIM];  // 28 KB
    __shared__ __align__(16) float  s_val[2][VPAD];           // 18.4 KB
    __shared__ float  wA[2][8], wP[2][8];
    __shared__ double sA[8], sB[8];
    __shared__ float  s_mean, s_scale;

    const int bid  = blockIdx.x;
    const int tid  = threadIdx.x;
    const int lane = tid & 31;
    const int warp = tid >> 5;
    const int t0   = tid << 3;                    // 8 elements per thread
    const unsigned full = 0xffffffffu;

    const int nrows = (bid < FULL_ROWS_CTAS) ? MAX_ROWS : (MAX_ROWS - 1);

    // ===================== Phase A: GAE scan per row =====================
    double dS1 = 0.0, dS2 = 0.0;

    // Prologue: stage row 0's values into buffer 0 via cp.async
    {
        const float* vrow = values + (size_t)bid * (T_DIM + 1);
        unsigned base = (unsigned)__cvta_generic_to_shared(&s_val[0][0]);
        #pragma unroll
        for (int j = 0; j < 8; ++j) {
            int st = tid + j * 256;
            CP_ASYNC_F32(base + (unsigned)vp(st) * 4u, vrow + st);
        }
        if (tid == 0) CP_ASYNC_F32(base + (unsigned)vp(2048) * 4u, vrow + 2048);
        CP_COMMIT();
    }

    for (int i = 0; i < nrows; ++i) {
        const int b   = bid + i * GRID;
        const int buf = i & 1;

        // Independent coalesced loads first (overlap with cp.async wait)
        const float* rr = rewards + (size_t)b * T_DIM + t0;
        const float* mm = masks   + (size_t)b * T_DIM + t0;
        float4 rA = __ldcs((const float4*)(rr));
        float4 rB = __ldcs((const float4*)(rr + 4));
        float4 mA = __ldcs((const float4*)(mm));
        float4 mB = __ldcs((const float4*)(mm + 4));

        // Prefetch this row's phase-B prob data into L2.
        // One row = 2048 floats = 64 x 128B lines each for old and curr.
        {
            const char* ob = (const char*)(oldp  + (size_t)b * T_DIM);
            const char* cb = (const char*)(currp + (size_t)b * T_DIM);
            if (tid < 64)            L2_PREFETCH(ob + (size_t)tid * 128);
            else if (tid < 128)      L2_PREFETCH(cb + (size_t)(tid - 64) * 128);
        }

        CP_WAIT0();          // this row's values staged (this thread's view)
        __syncthreads();     // all threads' cp.async visible; prev row done

        // Read this row's values from padded smem (conflict-free, stride 9)
        float v[9];
        {
            const int vb = 9 * tid;
            #pragma unroll
            for (int j = 0; j < 8; ++j) v[j] = s_val[buf][vb + j];
            v[8] = s_val[buf][vb + 9];           // vp(t0+8) = 9*tid + 9
        }

        // Kick off NEXT row's values staging into the other buffer
        if (i + 1 < nrows) {
            const float* vrow2 = values + (size_t)(b + GRID) * (T_DIM + 1);
            unsigned base2 = (unsigned)__cvta_generic_to_shared(&s_val[buf ^ 1][0]);
            #pragma unroll
            for (int j = 0; j < 8; ++j) {
                int st = tid + j * 256;
                CP_ASYNC_F32(base2 + (unsigned)vp(st) * 4u, vrow2 + st);
            }
            if (tid == 0) CP_ASYNC_F32(base2 + (unsigned)vp(2048) * 4u, vrow2 + 2048);
            CP_COMMIT();
        }

        float r[8] = {rA.x, rA.y, rA.z, rA.w, rB.x, rB.y, rB.z, rB.w};
        float m[8] = {mA.x, mA.y, mA.z, mA.w, mB.x, mB.y, mB.z, mB.w};

        float delta[8], c[8];
        #pragma unroll
        for (int j = 0; j < 8; ++j) {
            delta[j] = r[j] + kGamma * v[j + 1] * m[j] - v[j];
            c[j]     = kGL * m[j];
        }

        // Thread-local reverse scan summary (A, P): x -> A + P*x
        float A = 0.f, P = 1.f;
        #pragma unroll
        for (int j = 7; j >= 0; --j) { A = delta[j] + c[j] * A; P *= c[j]; }

        // Warp inclusive SUFFIX scan (higher lanes = higher t, applied first)
        float Ai = A, Pi = P;
        #pragma unroll
        for (int d = 1; d < 32; d <<= 1) {
            float Ah = __shfl_down_sync(full, Ai, d);
            float Ph = __shfl_down_sync(full, Pi, d);
            if (lane + d < 32) { Ai = Ai + Pi * Ah; Pi = Pi * Ph; }
        }

        if (lane == 0) { wA[buf][warp] = Ai; wP[buf][warp] = Pi; }
        __syncthreads();     // wA/wP[buf] ready (double-buffered per parity)

        // Carry entering this warp: compose warps 7..warp+1 applied to 0
        float warpCarry = 0.f;
        #pragma unroll
        for (int w = 7; w >= 0; --w)
            if (w > warp) warpCarry = wA[buf][w] + wP[buf][w] * warpCarry;

        // Exclusive-within-warp transform = inclusive suffix of lane+1
        float Ae = __shfl_down_sync(full, Ai, 1);
        float Pe = __shfl_down_sync(full, Pi, 1);
        if (lane == 31) { Ae = 0.f; Pe = 1.f; }
        float carry = Ae + Pe * warpCarry;

        // Final local values with real carry (in place into delta[])
        {
            float a = carry;
            #pragma unroll
            for (int j = 7; j >= 0; --j) { a = delta[j] + c[j] * a; delta[j] = a; }
        }

        // Stash advantages in shared memory as fp16 (one 16B STS)
        {
            __half2 h01 = __floats2half2_rn(delta[0], delta[1]);
            __half2 h23 = __floats2half2_rn(delta[2], delta[3]);
            __half2 h45 = __floats2half2_rn(delta[4], delta[5]);
            __half2 h67 = __floats2half2_rn(delta[6], delta[7]);
            uint4 pk;
            pk.x = *reinterpret_cast<unsigned*>(&h01);
            pk.y = *reinterpret_cast<unsigned*>(&h23);
            pk.z = *reinterpret_cast<unsigned*>(&h45);
            pk.w = *reinterpret_cast<unsigned*>(&h67);
            ((uint4*)s_adv)[(i * T_DIM + t0) >> 3] = pk;
        }

        // Accumulate sum/sumsq from full-precision adv (exact value_loss)
        float fs = 0.f, fq = 0.f;
        #pragma unroll
        for (int j = 0; j < 8; ++j) { fs += delta[j]; fq += delta[j] * delta[j]; }
        dS1 += (double)fs;
        dS2 += (double)fq;
    }

    // Block-reduce S1/S2 (double), one atomic pair per CTA
    #pragma unroll
    for (int d = 16; d > 0; d >>= 1) {
        dS1 += __shfl_down_sync(full, dS1, d);
        dS2 += __shfl_down_sync(full, dS2, d);
    }
    if (lane == 0) { sA[warp] = dS1; sB[warp] = dS2; }
    __syncthreads();
    if (tid == 0) {
        double ts = 0.0, tq = 0.0;
        #pragma unroll
        for (int w = 0; w < 8; ++w) { ts += sA[w]; tq += sB[w]; }
        atomicAdd(&g_S1, ts);
        atomicAdd(&g_S2, tq);
    }

    // Prefetch phase B's first row into registers while the barrier settles
    const float4* op_pf = (const float4*)(oldp  + (size_t)bid * T_DIM + t0);
    const float4* cp_pf = (const float4*)(currp + (size_t)bid * T_DIM + t0);
    float4 o0 = __ldcs(op_pf);
    float4 o1 = __ldcs(op_pf + 1);
    float4 c0 = __ldcs(cp_pf);
    float4 c1 = __ldcs(cp_pf + 1);

    // ===================== Grid-wide barrier + mean/std ==================
    if (tid == 0) {
        __threadfence();                          // order S1/S2 before arrival
        unsigned ticket = atomicAdd(&g_arrive1, 1u);
        if (ticket == (unsigned)(GRID - 1)) {
            double ts1 = atomicAdd(&g_S1, 0.0);   // coherent reads
            double ts2 = atomicAdd(&g_S2, 0.0);
            const double N = (double)N_ELEM;
            double mean = ts1 / N;
            double var  = (ts2 - N * mean * mean) / (N - 1.0);  // ddof=1
            g_mean_f  = (float)mean;
            g_scale_f = (float)(1.0 / (sqrt(var) + 1e-9));
            __threadfence();
            g_release = 1u;
        } else {
            while (g_release == 0u) __nanosleep(64);
            __threadfence();
        }
        s_mean  = g_mean_f;
        s_scale = g_scale_f;
    }
    __syncthreads();
    const float mean  = s_mean;
    const float scale = s_scale;

    // ===================== Phase B: surrogate + entropy ==================
    // min(surr1,surr2) = a>=0 ? min(ratio,1.2)*a : max(ratio,0.8)*a
    float fmin_acc = 0.f, fent_acc = 0.f;

    for (int i = 0; i < nrows; ++i) {
        // Kick off next row's loads before consuming this row (L2 hits now)
        float4 no0, no1, nc0, nc1;
        if (i + 1 < nrows) {
            const int bn = bid + (i + 1) * GRID;
            const float4* opn = (const float4*)(oldp  + (size_t)bn * T_DIM + t0);
            const float4* cpn = (const float4*)(currp + (size_t)bn * T_DIM + t0);
            no0 = __ldcs(opn);
            no1 = __ldcs(opn + 1);
            nc0 = __ldcs(cpn);
            nc1 = __ldcs(cpn + 1);
        }

        uint4 u = ((const uint4*)s_adv)[(i * T_DIM + t0) >> 3];
        float2 a01 = __half22float2(*reinterpret_cast<__half2*>(&u.x));
        float2 a23 = __half22float2(*reinterpret_cast<__half2*>(&u.y));
        float2 a45 = __half22float2(*reinterpret_cast<__half2*>(&u.z));
        float2 a67 = __half22float2(*reinterpret_cast<__half2*>(&u.w));

        float av[8] = {a01.x, a01.y, a23.x, a23.y, a45.x, a45.y, a67.x, a67.y};
        float ov[8] = {o0.x, o0.y, o0.z, o0.w, o1.x, o1.y, o1.z, o1.w};
        float cv[8] = {c0.x, c0.y, c0.z, c0.w, c1.x, c1.y, c1.z, c1.w};

        #pragma unroll
        for (int k = 0; k < 8; ++k) {
            float an    = (av[k] - mean) * scale;
            float ratio = __fdividef(cv[k], ov[k] + kEps);
            float t = (an >= 0.f) ? fminf(ratio, 1.2f) * an
                                  : fmaxf(ratio, 0.8f) * an;
            fmin_acc += t;
            fent_acc += cv[k] * __logf(cv[k] + kEps);
        }

        o0 = no0; o1 = no1; c0 = nc0; c1 = nc1;
    }

    double lmin = (double)fmin_acc, lent = (double)fent_acc;
    #pragma unroll
    for (int d = 16; d > 0; d >>= 1) {
        lmin += __shfl_down_sync(full, lmin, d);
        lent += __shfl_down_sync(full, lent, d);
    }
    if (lane == 0) { sA[warp] = lmin; sB[warp] = lent; }
    __syncthreads();

    if (tid == 0) {
        double tm = 0.0, te = 0.0;
        #pragma unroll
        for (int w = 0; w < 8; ++w) { tm += sA[w]; te += sB[w]; }
        atomicAdd(&g_MIN, tm);
        atomicAdd(&g_ENT, te);
        __threadfence();                  // order loss atomics before arrival
        unsigned done = atomicAdd(&g_arrive2, 1u);
        if (done == (unsigned)(GRID - 1)) {
            // Last CTA: finalize output, reset ALL state for the next launch.
            double tmin = atomicAdd(&g_MIN, 0.0);
            double tent = atomicAdd(&g_ENT, 0.0);
            double ts2  = atomicAdd(&g_S2,  0.0);
            const double N = (double)N_ELEM;
            double ppo = -(tmin / N);
            double vl  = 0.5   * (ts2  / N);  // VALUE_LOSS_COEF * mean(adv^2)
            double ent = -0.01 * (tent / N);  // ENTROPY_COEF * entropy_loss
            out[0] = (float)(ppo + vl + ent);
            out[1] = (float)ppo;
            out[2] = (float)vl;
            out[3] = (float)ent;
            g_S1 = 0.0; g_S2 = 0.0; g_MIN = 0.0; g_ENT = 0.0;
            g_arrive1 = 0u; g_arrive2 = 0u;
            g_mean_f = 0.f; g_scale_f = 0.f;
            __threadfence();
            g_release = 0u;               // safe: every CTA is past barrier 1
        }
    }
}

extern "C" void kernel_launch(void* const* d_in, const int* in_sizes, int n_in,
                              void* d_out, int out_size)
{
    const float* rewards = (const float*)d_in[0];
    const float* values  = (const float*)d_in[1];
    // d_in[2] = ref_probs (unused by reference)
    const float* oldp    = (const float*)d_in[3];
    const float* currp   = (const float*)d_in[4];
    const float* masks   = (const float*)d_in[5];

    ppo_fused_kernel<<<GRID, 256>>>(rewards, values, masks, oldp, currp,
                                    (float*)d_out);
}